// round 4
// baseline (speedup 1.0000x reference)
#include <cuda_runtime.h>

#define H_IN   200
#define W_IN   320
#define C_IN   64
#define H_OUT  48
#define W_OUT  320

__global__ void roi_crop_kernel(const float* __restrict__ x,
                                const int*   __restrict__ bboxes,
                                const int*   __restrict__ box_img,
                                float*       __restrict__ out)
{
    const int i = blockIdx.x;   // output row, 0..47
    const int b = blockIdx.y;   // box index, 0..255
    const int t = threadIdx.x;  // 0..255

    __shared__ int s_cols[W_OUT];

    // Load + clip bbox (broadcast loads, L1/L2 cached)
    int x0 = bboxes[b * 4 + 0];
    int y0 = bboxes[b * 4 + 1];
    int x1 = bboxes[b * 4 + 2];
    int y1 = bboxes[b * 4 + 3];
    x0 = min(max(x0, 0), W_IN - 1);
    y0 = min(max(y0, 0), H_IN - 1);
    x1 = min(max(x1, 0), W_IN - 1);
    y1 = min(max(y1, 0), H_IN - 1);
    x1 = max(x1, x0);
    y1 = max(y1, y0);
    const int h = y1 - y0 + 1;
    const int w = x1 - x0 + 1;

    const int r = y0 + (i * h) / H_OUT;   // source row for this output row

    // Precompute the 320 source columns for this box
    for (int j = t; j < W_OUT; j += blockDim.x)
        s_cols[j] = x0 + (j * w) / W_OUT;
    __syncthreads();

    const int img = box_img[b];

    // 64 channels * 80 float4 units per channel = 5120 work units
    const size_t x_img_base  = (size_t)img * C_IN * H_IN * W_IN + (size_t)r * W_IN;
    const size_t out_box_base = ((size_t)b * C_IN * H_OUT + i) * W_OUT;

    #pragma unroll 4
    for (int u = t; u < C_IN * (W_OUT / 4); u += 256) {
        const int c = u / (W_OUT / 4);
        const int q = u % (W_OUT / 4);
        const float* __restrict__ src = x + x_img_base + (size_t)c * (H_IN * W_IN);
        const int j = q * 4;
        float4 v;
        v.x = __ldg(src + s_cols[j + 0]);
        v.y = __ldg(src + s_cols[j + 1]);
        v.z = __ldg(src + s_cols[j + 2]);
        v.w = __ldg(src + s_cols[j + 3]);
        float4* __restrict__ dst =
            (float4*)(out + out_box_base + (size_t)c * (H_OUT * W_OUT));
        dst[q] = v;
    }
}

extern "C" void kernel_launch(void* const* d_in, const int* in_sizes, int n_in,
                              void* d_out, int out_size)
{
    const float* x       = (const float*)d_in[0];
    const int*   bboxes  = (const int*)d_in[1];
    const int*   box_img = (const int*)d_in[2];
    float*       out     = (float*)d_out;

    dim3 grid(H_OUT, 256);   // (48 rows, 256 boxes)
    roi_crop_kernel<<<grid, 256>>>(x, bboxes, box_img, out);
}